// round 6
// baseline (speedup 1.0000x reference)
#include <cuda_runtime.h>

// Downsample1d: depthwise FIR [1/8, 3/8, 3/8, 1/8], stride 2, reflect pad 1.
// x: [B=8, C=128, T=65536] fp32 -> out: [B, C, T/2=32768] fp32.
// out[n] = 0.125*(x[2n-1] + x[2n+2]) + 0.375*(x[2n] + x[2n+1])
// reflect: x[-1] = x[1], x[T] = x[T-2]   (per row)

#define T_IN   65536
#define T_OUT  32768
#define VECS_PER_ROW (T_OUT / 4)   // 8192: each thread makes 4 outputs
#define N_ROWS (8 * 128)

__global__ __launch_bounds__(256) void downsample1d_kernel(
    const float* __restrict__ x, float* __restrict__ out)
{
    long long v = (long long)blockIdx.x * blockDim.x + threadIdx.x;
    // total = N_ROWS * VECS_PER_ROW = 8,388,608 threads; grid sized exactly.
    int row = (int)(v >> 13);          // v / 8192
    int j   = (int)(v & 8191);         // v % 8192

    const float* xr = x + (long long)row * T_IN;
    int m = j << 3;                    // input window start: 8*j

    // Two aligned 16B loads: x[m..m+3], x[m+4..m+7]
    float4 a = *reinterpret_cast<const float4*>(xr + m);
    float4 b = *reinterpret_cast<const float4*>(xr + m + 4);

    // Halo elements (reflect at row edges). Interior loads are L1/L2 sector
    // hits: they alias neighboring threads' vector loads.
    float prev = (j == 0)               ? xr[1]          : xr[m - 1];
    float next = (j == VECS_PER_ROW - 1) ? xr[T_IN - 2]  : xr[m + 8];

    const float w0 = 0.125f, w1 = 0.375f;

    float4 o;
    o.x = w0 * (prev + a.z) + w1 * (a.x + a.y);
    o.y = w0 * (a.y  + b.x) + w1 * (a.z + a.w);
    o.z = w0 * (a.w  + b.z) + w1 * (b.x + b.y);
    o.w = w0 * (b.y  + next) + w1 * (b.z + b.w);

    *reinterpret_cast<float4*>(out + (long long)row * T_OUT + (j << 2)) = o;
}

extern "C" void kernel_launch(void* const* d_in, const int* in_sizes, int n_in,
                              void* d_out, int out_size)
{
    const float* x = (const float*)d_in[0];
    // d_in[1] is the fixed kernel taps; baked in as constants.
    float* out = (float*)d_out;

    const long long total = (long long)N_ROWS * VECS_PER_ROW; // 8,388,608
    const int threads = 256;
    const int blocks = (int)(total / threads);                // 32768
    downsample1d_kernel<<<blocks, threads>>>(x, out);
}